// round 13
// baseline (speedup 1.0000x reference)
#include <cuda_runtime.h>
#include <math.h>
#include <stdint.h>

// ---------------- problem constants ----------------
#define Bb   64
#define Ss   256
#define Tt   128
#define Ee   256
#define Hh   512
#define Dd   1024
#define VTt  8192
#define SB   (Ss*Bb)   // 16384

// ---------------- scratch (device globals; allocations are forbidden) ------
__device__ __align__(256) float g_xs[SB*Ee];
__device__ __align__(256) float g_gi[2*SB*1536];
__device__ __align__(256) float g_y0[SB*Dd];
__device__ __align__(256) float g_enc_out[Bb*Ss*Dd];
__device__ __align__(256) float g_enc_score[Bb*Ss];
__device__ __align__(256) float g_h[2*2*Bb*Hh];
__device__ __align__(256) float g_ghp[3*2*Bb*1536];
__device__ __align__(256) float g_dh0[Bb*Dd];
__device__ __align__(256) float g_dh1[Bb*Dd];
__device__ __align__(256) float g_xdec[Bb*1280];
__device__ __align__(256) float g_gpa[6*Bb*3072];   // gi partials (3 for gi0, 6 for gi1)
__device__ __align__(256) float g_gpb[3*Bb*3072];   // gh0 partials
__device__ __align__(256) float g_gpc[3*Bb*3072];   // gh1 partials
__device__ unsigned g_cnt[4];

// ---------------- software grid barrier ----------------
__device__ __forceinline__ void gsync(unsigned* cnt, unsigned target) {
    __threadfence();
    __syncthreads();
    if (threadIdx.x == 0) {
        atomicAdd(cnt, 1u);
        while (*(volatile unsigned*)cnt < target) { __nanosleep(64); }
    }
    __syncthreads();
    __threadfence();
}

// ---------------- tf32 helpers ----------------
__device__ __forceinline__ uint32_t f2tf(float x) {
    uint32_t r; asm("cvt.rna.tf32.f32 %0, %1;" : "=r"(r) : "f"(x)); return r;
}
__device__ __forceinline__ void mma8(float* d, const uint32_t* a, const uint32_t* b) {
    asm volatile("mma.sync.aligned.m16n8k8.row.col.f32.tf32.tf32.f32 "
        "{%0,%1,%2,%3}, {%4,%5,%6,%7}, {%8,%9}, {%0,%1,%2,%3};"
        : "+f"(d[0]), "+f"(d[1]), "+f"(d[2]), "+f"(d[3])
        : "r"(a[0]), "r"(a[1]), "r"(a[2]), "r"(a[3]), "r"(b[0]), "r"(b[1]));
}

// ---------------- tf32 mma tile: C(64,NT) (+)= A(64,k0:kend) @ W(NT,k)^T ---
// 256 threads = 8 warps; warp grid 2(M)x4(N); warp tile 32 x (NT/4).
// A read via __ldcg (produced by other SMs inside persistent kernels).
// k0/kend multiples of 16. lda/ldw multiples of 4.
template<int NT>
__device__ void mma_tile(float* sm,
    const float* __restrict__ A, int lda,
    const float* __restrict__ W, int ldw,
    float* __restrict__ C, long long ldc,
    const float* __restrict__ bias, int k0, int kend)
{
    constexpr int PAD = 20;
    float* As = sm;               // [64][20]
    float* Ws = sm + 64 * PAD;    // [NT][20]
    const int tid = threadIdx.x;
    const int wid = tid >> 5, lane = tid & 31;
    const int lq = lane >> 2, lr = lane & 3;
    const int wm = (wid >> 2) * 32;
    const int wn = (wid & 3) * (NT / 4);
    constexpr int NJ = NT / 32;           // n8 tiles per warp (4 or 2)
    constexpr int WL = NT / 64;           // W float4 loads per thread (2 or 1)

    float d[2][NJ][4];
    #pragma unroll
    for (int i = 0; i < 2; i++)
        #pragma unroll
        for (int j = 0; j < NJ; j++)
            { d[i][j][0]=0.f; d[i][j][1]=0.f; d[i][j][2]=0.f; d[i][j][3]=0.f; }

    const int ar = tid >> 2;          // 0..63
    const int ac = (tid & 3) << 2;    // 0,4,8,12

    float4 apre, wpre[WL];
    apre = __ldcg((const float4*)(A + (long long)ar * lda + k0 + ac));
    #pragma unroll
    for (int j = 0; j < WL; j++)
        wpre[j] = *(const float4*)(W + (long long)(ar + j * 64) * ldw + k0 + ac);

    for (int kk = k0; kk < kend; kk += 16) {
        float* ap = As + ar * PAD + ac;
        ap[0] = __uint_as_float(f2tf(apre.x)); ap[1] = __uint_as_float(f2tf(apre.y));
        ap[2] = __uint_as_float(f2tf(apre.z)); ap[3] = __uint_as_float(f2tf(apre.w));
        #pragma unroll
        for (int j = 0; j < WL; j++) {
            float* wp = Ws + (ar + j * 64) * PAD + ac;
            wp[0] = __uint_as_float(f2tf(wpre[j].x)); wp[1] = __uint_as_float(f2tf(wpre[j].y));
            wp[2] = __uint_as_float(f2tf(wpre[j].z)); wp[3] = __uint_as_float(f2tf(wpre[j].w));
        }
        __syncthreads();
        if (kk + 16 < kend) {
            apre = __ldcg((const float4*)(A + (long long)ar * lda + kk + 16 + ac));
            #pragma unroll
            for (int j = 0; j < WL; j++)
                wpre[j] = *(const float4*)(W + (long long)(ar + j * 64) * ldw + kk + 16 + ac);
        }
        #pragma unroll
        for (int k8 = 0; k8 < 16; k8 += 8) {
            uint32_t a[2][4];
            #pragma unroll
            for (int i = 0; i < 2; i++) {
                const float* p = As + (wm + i * 16 + lq) * PAD + k8 + lr;
                a[i][0] = __float_as_uint(p[0]);
                a[i][1] = __float_as_uint(p[8 * PAD]);
                a[i][2] = __float_as_uint(p[4]);
                a[i][3] = __float_as_uint(p[8 * PAD + 4]);
            }
            #pragma unroll
            for (int j = 0; j < NJ; j++) {
                const float* q = Ws + (wn + j * 8 + lq) * PAD + k8 + lr;
                uint32_t b[2] = { __float_as_uint(q[0]), __float_as_uint(q[4]) };
                #pragma unroll
                for (int i = 0; i < 2; i++) mma8(d[i][j], a[i], b);
            }
        }
        __syncthreads();
    }

    #pragma unroll
    for (int i = 0; i < 2; i++) {
        int row = wm + i * 16 + lq;
        #pragma unroll
        for (int j = 0; j < NJ; j++) {
            int col = wn + j * 8 + lr * 2;
            float b0 = 0.f, b1 = 0.f;
            if (bias) { b0 = bias[col]; b1 = bias[col + 1]; }
            float2 v0 = make_float2(d[i][j][0] + b0, d[i][j][1] + b1);
            float2 v1 = make_float2(d[i][j][2] + b0, d[i][j][3] + b1);
            *(float2*)(C + (long long)row * ldc + col) = v0;
            *(float2*)(C + (long long)(row + 8) * ldc + col) = v1;
        }
    }
}

// ---------------- tiny utility kernels ----------------
__global__ void k_init(float* h) {
    int i = blockIdx.x * 256 + threadIdx.x;   // 131072 threads
    h[i] = 0.f;
    if (i < 4) g_cnt[i] = 0u;
}

__global__ void k_embed(const int* __restrict__ src, const float* __restrict__ emb,
                        float* __restrict__ xs) {
    int i = blockIdx.x * 256 + threadIdx.x;
    int e = i & 255;
    int b = (i >> 8) & 63;
    int t = i >> 14;
    xs[i] = emb[src[b * Ss + t] * Ee + e];
}

__global__ void k_decprep(const float* __restrict__ henc,
                          float* __restrict__ h0, float* __restrict__ h1,
                          const float* __restrict__ enc_out,
                          const float* __restrict__ attn_W,
                          const float* __restrict__ attn_b,
                          float* __restrict__ enc_score,
                          float* __restrict__ out)
{
    long long gi0 = (long long)blockIdx.x * 256 + threadIdx.x;
    if (gi0 < 131072) {
        int k = (int)(gi0 & 1023);
        int b = (int)((gi0 >> 10) & 63);
        int layer = (int)(gi0 >> 16);
        int dir = k >> 9;
        float v = henc[layer * 2 * Bb * Hh + dir * Bb * Hh + b * Hh + (k & 511)];
        (layer ? h1 : h0)[b * Dd + k] = v;
    }
    if (gi0 < 524288) {
        int b = (int)(gi0 >> 13);
        out[(long long)b * Tt * VTt + (gi0 & 8191)] = 0.f;
    }
    {
        int wrp = (int)(gi0 >> 5);
        int lane = threadIdx.x & 31;
        const float* row = enc_out + (long long)wrp * 1024;
        float s = 0.f;
        for (int k = lane; k < 1024; k += 32)
            s += row[k] * attn_W[1024 + k];
        #pragma unroll
        for (int o = 16; o > 0; o >>= 1)
            s += __shfl_down_sync(0xffffffffu, s, o);
        if (lane == 0) enc_score[wrp] = s + attn_b[0];
    }
}

// ---------------- big tf32 GEMM (time-parallel gi projections) -------------
// C(M,1536) = A(M,K) @ W(1536,K)^T + bias.  grid (12, M/64)
__global__ void __launch_bounds__(256) k_gemm_big(
    const float* __restrict__ A, int lda,
    const float* __restrict__ W,
    const float* __restrict__ bias,
    float* __restrict__ C, int K)
{
    __shared__ float sm[(64 + 128) * 20];
    const int nt = blockIdx.x, mt = blockIdx.y;
    mma_tile<128>(sm, A + (long long)mt * 64 * lda, lda,
                  W + (long long)nt * 128 * K, K,
                  C + (long long)mt * 64 * 1536 + nt * 128, 1536,
                  bias + nt * 128, 0, K);
}

// ---------------- persistent encoder layer (grid = 144 blocks) -------------
// jobs: 3 ksplit x 2 dir x 24 n64-tiles = 144
__global__ void __launch_bounds__(256) k_enc(
    const float* __restrict__ gi, const float* __restrict__ Whh,
    const float* __restrict__ bhh, float* __restrict__ h,
    float* __restrict__ y, float* __restrict__ ghp, int mode, unsigned* cnt)
{
    __shared__ float sm[(64 + 64) * 20];
    const int bid = blockIdx.x;
    unsigned bt = 0;

    const int z = bid / 48, rem = bid % 48;
    const int dir = rem / 24, nt = rem % 24;
    const int k0 = z * 176, kend = (z == 2) ? 512 : (k0 + 176);
    const float* Ah = h + dir * 64 * 512;
    const float* Wt = Whh + (long long)dir * 1536 * 512 + (long long)nt * 64 * 512;
    float* Ct = ghp + (long long)z * 128 * 1536 + (long long)dir * 64 * 1536 + nt * 64;

    for (int t = 0; t < Ss; t++) {
        mma_tile<64>(sm, Ah, 512, Wt, 512, Ct, 1536, nullptr, k0, kend);
        gsync(cnt, bt += 144);

        for (int i = bid * 256 + threadIdx.x; i < 65536; i += 144 * 256) {
            int k = i & 511;
            int b = (i >> 9) & 63;
            int d2 = i >> 15;
            int row = d2 * 64 + b;
            int teff = d2 ? (255 - t) : t;

            long long gbase = ((long long)d2 * SB + (long long)teff * 64 + b) * 1536;
            float ir  = gi[gbase + k];
            float iz  = gi[gbase + 512 + k];
            float in_ = gi[gbase + 1024 + k];

            float hr = bhh[d2 * 1536 + k];
            float hz = bhh[d2 * 1536 + 512 + k];
            float hn = bhh[d2 * 1536 + 1024 + k];
            #pragma unroll
            for (int zz = 0; zz < 3; zz++) {
                long long p = (long long)zz * 128 * 1536 + (long long)row * 1536;
                hr += __ldcg(&ghp[p + k]);
                hz += __ldcg(&ghp[p + 512 + k]);
                hn += __ldcg(&ghp[p + 1024 + k]);
            }

            float hv = __ldcg(&h[row * 512 + k]);
            float r  = 1.f / (1.f + expf(-(ir + hr)));
            float zg = 1.f / (1.f + expf(-(iz + hz)));
            float n  = tanhf(in_ + r * hn);
            float hnew = (1.f - zg) * n + zg * hv;
            h[row * 512 + k] = hnew;

            if (mode == 0)
                y[((long long)teff * 64 + b) * 1024 + d2 * 512 + k] = hnew;
            else
                y[(long long)b * Ss * Dd + (long long)teff * Dd + d2 * 512 + k] = hnew;
        }
        gsync(cnt, bt += 144);
    }
}

// ---------------- decoder GRU combine ----------------
__device__ __forceinline__ void dec_combine(
    const float* __restrict__ gi_, int ngi,
    const float* __restrict__ gh_, int ngh,
    const float* __restrict__ bih, const float* __restrict__ bhh,
    float* __restrict__ h)
{
    for (int i = blockIdx.x * 256 + threadIdx.x; i < 65536; i += 148 * 256) {
        int k = i & 1023;
        int b = i >> 10;
        float ir = bih[k], iz = bih[1024 + k], in_ = bih[2048 + k];
        float hr = bhh[k], hz = bhh[1024 + k], hn  = bhh[2048 + k];
        for (int z = 0; z < ngi; z++) {
            long long p = (long long)z * 64 * 3072 + (long long)b * 3072;
            ir += __ldcg(&gi_[p + k]); iz += __ldcg(&gi_[p + 1024 + k]); in_ += __ldcg(&gi_[p + 2048 + k]);
        }
        for (int z = 0; z < ngh; z++) {
            long long p = (long long)z * 64 * 3072 + (long long)b * 3072;
            hr += __ldcg(&gh_[p + k]); hz += __ldcg(&gh_[p + 1024 + k]); hn += __ldcg(&gh_[p + 2048 + k]);
        }
        float hv = __ldcg(&h[b * 1024 + k]);
        float r  = 1.f / (1.f + expf(-(ir + hr)));
        float zg = 1.f / (1.f + expf(-(iz + hz)));
        float n  = tanhf(in_ + r * hn);
        h[b * 1024 + k] = (1.f - zg) * n + zg * hv;
    }
}

// ---------------- persistent decoder (grid = 148 blocks) -------------------
__global__ void __launch_bounds__(256) k_dec(
    const float* __restrict__ enc_out, const float* __restrict__ enc_score,
    const int* __restrict__ tgt, const float* __restrict__ tgt_emb,
    const float* __restrict__ attn_W,
    const float* __restrict__ dWih0, const float* __restrict__ dWhh0,
    const float* __restrict__ dbih0, const float* __restrict__ dbhh0,
    const float* __restrict__ dWih1, const float* __restrict__ dWhh1,
    const float* __restrict__ dbih1, const float* __restrict__ dbhh1,
    const float* __restrict__ out_W, const float* __restrict__ out_b,
    float* __restrict__ dh0, float* __restrict__ dh1,
    float* __restrict__ xdec,
    float* __restrict__ gpa, float* __restrict__ gpb, float* __restrict__ gpc,
    float* __restrict__ out, unsigned* cnt)
{
    __shared__ float sm[(64 + 128) * 20];
    __shared__ float red[256];
    __shared__ float sc[256];
    const int bid = blockIdx.x;
    const int tid = threadIdx.x;
    unsigned bt = 0;

    for (int t = 0; t < Tt - 1; t++) {
        // ---- Phase A: logits(t-1) [64 jobs] + attention(t) [64 jobs] ----
        if (bid < 64) {
            if (t > 0)
                mma_tile<128>(sm, dh1, 1024, out_W + (long long)bid * 128 * 1024, 1024,
                              out + (long long)t * VTt + bid * 128, (long long)Tt * VTt,
                              out_b + bid * 128, 0, 1024);
        } else if (bid < 128) {
            int b = bid - 64;
            float p = 0.f;
            #pragma unroll
            for (int j = tid; j < 1024; j += 256)
                p += __ldcg(&dh1[b * 1024 + j]) * attn_W[j];
            red[tid] = p; __syncthreads();
            for (int q = 128; q > 0; q >>= 1) { if (tid < q) red[tid] += red[tid + q]; __syncthreads(); }
            float qv = red[0];
            __syncthreads();

            float v = enc_score[b * 256 + tid] + qv;
            red[tid] = v; __syncthreads();
            for (int q = 128; q > 0; q >>= 1) { if (tid < q) red[tid] = fmaxf(red[tid], red[tid + q]); __syncthreads(); }
            float mx = red[0];
            __syncthreads();
            float e = expf(v - mx);
            red[tid] = e; __syncthreads();
            for (int q = 128; q > 0; q >>= 1) { if (tid < q) red[tid] += red[tid + q]; __syncthreads(); }
            sc[tid] = e / red[0];
            __syncthreads();

            float4 acc = make_float4(0.f, 0.f, 0.f, 0.f);
            const float4* eo = (const float4*)(enc_out + (long long)b * Ss * Dd);
            #pragma unroll 4
            for (int sIdx = 0; sIdx < 256; sIdx++) {
                float w = sc[sIdx];
                float4 ev = eo[sIdx * 256 + tid];
                acc.x += w * ev.x; acc.y += w * ev.y; acc.z += w * ev.z; acc.w += w * ev.w;
            }
            *(float4*)&xdec[b * 1280 + 256 + tid * 4] = acc;
            xdec[b * 1280 + tid] = tgt_emb[tgt[b * Tt + t] * 256 + tid];
        }
        gsync(cnt, bt += 148);

        // ---- Phase B: gi0 (72 jobs, K=1280 split3) + gh0 (72) + gh1 (72) ----
        for (int job = bid; job < 216; job += 148) {
            if (job < 72) {
                int z = job / 24, nt = job % 24;
                int k0 = z * 432, ke = (z == 2) ? 1280 : (k0 + 432);
                mma_tile<128>(sm, xdec, 1280, dWih0 + (long long)nt * 128 * 1280, 1280,
                              gpa + (long long)z * 64 * 3072 + nt * 128, 3072, nullptr, k0, ke);
            } else if (job < 144) {
                int j = job - 72; int z = j / 24, nt = j % 24;
                int k0 = (z == 0) ? 0 : (z == 1 ? 352 : 688);
                int ke = (z == 0) ? 352 : (z == 1 ? 688 : 1024);
                mma_tile<128>(sm, dh0, 1024, dWhh0 + (long long)nt * 128 * 1024, 1024,
                              gpb + (long long)z * 64 * 3072 + nt * 128, 3072, nullptr, k0, ke);
            } else {
                int j = job - 144; int z = j / 24, nt = j % 24;
                int k0 = (z == 0) ? 0 : (z == 1 ? 352 : 688);
                int ke = (z == 0) ? 352 : (z == 1 ? 688 : 1024);
                mma_tile<128>(sm, dh1, 1024, dWhh1 + (long long)nt * 128 * 1024, 1024,
                              gpc + (long long)z * 64 * 3072 + nt * 128, 3072, nullptr, k0, ke);
            }
        }
        gsync(cnt, bt += 148);

        // ---- Phase C: combine h0 ----
        dec_combine(gpa, 3, gpb, 3, dbih0, dbhh0, dh0);
        gsync(cnt, bt += 148);

        // ---- Phase D: gi1 (144 jobs, K=1024 split6) ----
        for (int job = bid; job < 144; job += 148) {
            int z = job / 24, nt = job % 24;
            int k0 = (z < 4) ? z * 176 : 704 + (z - 4) * 160;
            int ke = k0 + ((z < 4) ? 176 : 160);
            mma_tile<128>(sm, dh0, 1024, dWih1 + (long long)nt * 128 * 1024, 1024,
                          gpa + (long long)z * 64 * 3072 + nt * 128, 3072, nullptr, k0, ke);
        }
        gsync(cnt, bt += 148);

        // ---- Phase E: combine h1 ----
        dec_combine(gpa, 6, gpc, 3, dbih1, dbhh1, dh1);
        gsync(cnt, bt += 148);
    }

    // ---- final logits (t = 126 -> out[:, 127, :]) ----
    if (bid < 64)
        mma_tile<128>(sm, dh1, 1024, out_W + (long long)bid * 128 * 1024, 1024,
                      out + (long long)127 * VTt + bid * 128, (long long)Tt * VTt,
                      out_b + bid * 128, 0, 1024);
}

extern "C" void kernel_launch(void* const* d_in, const int* in_sizes, int n_in,
                              void* d_out, int out_size)
{
    const int*   src     = (const int*)  d_in[0];
    const int*   tgt     = (const int*)  d_in[1];
    const float* src_emb = (const float*)d_in[2];
    const float* tgt_emb = (const float*)d_in[3];
    const float* eWih0   = (const float*)d_in[4];
    const float* eWhh0   = (const float*)d_in[5];
    const float* ebih0   = (const float*)d_in[6];
    const float* ebhh0   = (const float*)d_in[7];
    const float* eWih1   = (const float*)d_in[8];
    const float* eWhh1   = (const float*)d_in[9];
    const float* ebih1   = (const float*)d_in[10];
    const float* ebhh1   = (const float*)d_in[11];
    const float* dWih0   = (const float*)d_in[12];
    const float* dWhh0   = (const float*)d_in[13];
    const float* dbih0   = (const float*)d_in[14];
    const float* dbhh0   = (const float*)d_in[15];
    const float* dWih1   = (const float*)d_in[16];
    const float* dWhh1   = (const float*)d_in[17];
    const float* dbih1   = (const float*)d_in[18];
    const float* dbhh1   = (const float*)d_in[19];
    const float* attn_W  = (const float*)d_in[20];
    const float* attn_b  = (const float*)d_in[21];
    const float* out_W   = (const float*)d_in[22];
    const float* out_b   = (const float*)d_in[23];
    float* out = (float*)d_out;

    float *xs, *gi, *y0, *enc_out, *enc_sc, *h, *ghp, *dh0, *dh1, *xdec, *gpa, *gpb, *gpc;
    unsigned* cnt;
    cudaGetSymbolAddress((void**)&xs,      g_xs);
    cudaGetSymbolAddress((void**)&gi,      g_gi);
    cudaGetSymbolAddress((void**)&y0,      g_y0);
    cudaGetSymbolAddress((void**)&enc_out, g_enc_out);
    cudaGetSymbolAddress((void**)&enc_sc,  g_enc_score);
    cudaGetSymbolAddress((void**)&h,       g_h);
    cudaGetSymbolAddress((void**)&ghp,     g_ghp);
    cudaGetSymbolAddress((void**)&dh0,     g_dh0);
    cudaGetSymbolAddress((void**)&dh1,     g_dh1);
    cudaGetSymbolAddress((void**)&xdec,    g_xdec);
    cudaGetSymbolAddress((void**)&gpa,     g_gpa);
    cudaGetSymbolAddress((void**)&gpb,     g_gpb);
    cudaGetSymbolAddress((void**)&gpc,     g_gpc);
    cudaGetSymbolAddress((void**)&cnt,     g_cnt);

    // ---- setup ----
    k_init<<<512, 256>>>(h);
    k_embed<<<(SB * Ee) / 256, 256>>>(src, src_emb, xs);

    // ---- encoder layer 0 ----
    for (int d = 0; d < 2; d++)
        k_gemm_big<<<dim3(12, SB / 64), 256>>>(xs, Ee, eWih0 + (size_t)d * 1536 * Ee,
                                               ebih0 + d * 1536,
                                               gi + (size_t)d * SB * 1536, Ee);
    k_enc<<<144, 256>>>(gi, eWhh0, ebhh0, h, y0, ghp, 0, cnt);

    // ---- encoder layer 1 ----
    for (int d = 0; d < 2; d++)
        k_gemm_big<<<dim3(12, SB / 64), 256>>>(y0, Dd, eWih1 + (size_t)d * 1536 * Dd,
                                               ebih1 + d * 1536,
                                               gi + (size_t)d * SB * 1536, Dd);
    k_enc<<<144, 256>>>(gi, eWhh1, ebhh1, h + 2 * Bb * Hh, enc_out, ghp, 1, cnt + 1);

    // ---- decoder prep ----
    k_decprep<<<2048, 256>>>(h, dh0, dh1, enc_out, attn_W, attn_b, enc_sc, out);

    // ---- decoder (persistent) ----
    k_dec<<<148, 256>>>(enc_out, enc_sc, tgt, tgt_emb, attn_W,
                        dWih0, dWhh0, dbih0, dbhh0,
                        dWih1, dWhh1, dbih1, dbhh1,
                        out_W, out_b, dh0, dh1, xdec, gpa, gpb, gpc, out, cnt + 2);
}

// round 14
// speedup vs baseline: 1.0013x; 1.0013x over previous
#include <cuda_runtime.h>
#include <math.h>
#include <stdint.h>

// ---------------- problem constants ----------------
#define Bb   64
#define Ss   256
#define Tt   128
#define Ee   256
#define Hh   512
#define Dd   1024
#define VTt  8192
#define SB   (Ss*Bb)   // 16384

// ---------------- scratch (device globals; allocations are forbidden) ------
__device__ __align__(256) float g_xs[SB*Ee];
__device__ __align__(256) float g_gi[2*SB*1536];
__device__ __align__(256) float g_y0[SB*Dd];
__device__ __align__(256) float g_enc_out[Bb*Ss*Dd];
__device__ __align__(256) float g_enc_score[Bb*Ss];
__device__ __align__(256) float g_h[2*2*Bb*Hh];
__device__ __align__(256) float g_ghp[3*2*Bb*1536];
__device__ __align__(256) float g_dh0[Bb*Dd];
__device__ __align__(256) float g_dh1[Bb*Dd];
__device__ __align__(256) float g_xdec[Bb*1280];
__device__ __align__(256) float g_gpa[6*Bb*3072];   // gi partials (3 for gi0, 6 for gi1)
__device__ __align__(256) float g_gpb[3*Bb*3072];   // gh0 partials
__device__ __align__(256) float g_gpc[3*Bb*3072];   // gh1 partials
__device__ unsigned g_cnt[4];

// ---------------- software grid barrier ----------------
__device__ __forceinline__ void gsync(unsigned* cnt, unsigned target) {
    __threadfence();
    __syncthreads();
    if (threadIdx.x == 0) {
        atomicAdd(cnt, 1u);
        while (*(volatile unsigned*)cnt < target) { __nanosleep(64); }
    }
    __syncthreads();
    __threadfence();
}

// ---------------- tf32 helpers ----------------
__device__ __forceinline__ uint32_t f2tf(float x) {
    uint32_t r; asm("cvt.rna.tf32.f32 %0, %1;" : "=r"(r) : "f"(x)); return r;
}
__device__ __forceinline__ void mma8(float* d, const uint32_t* a, const uint32_t* b) {
    asm volatile("mma.sync.aligned.m16n8k8.row.col.f32.tf32.tf32.f32 "
        "{%0,%1,%2,%3}, {%4,%5,%6,%7}, {%8,%9}, {%0,%1,%2,%3};"
        : "+f"(d[0]), "+f"(d[1]), "+f"(d[2]), "+f"(d[3])
        : "r"(a[0]), "r"(a[1]), "r"(a[2]), "r"(a[3]), "r"(b[0]), "r"(b[1]));
}

// ---------------- tf32 mma tile: C(64,NT) (+)= A(64,k0:kend) @ W(NT,k)^T ---
// 256 threads = 8 warps; warp grid 2(M)x4(N); warp tile 32 x (NT/4).
// A read via __ldcg (produced by other SMs inside persistent kernels).
// k0/kend multiples of 16. lda/ldw multiples of 4.
template<int NT>
__device__ void mma_tile(float* sm,
    const float* __restrict__ A, int lda,
    const float* __restrict__ W, int ldw,
    float* __restrict__ C, long long ldc,
    const float* __restrict__ bias, int k0, int kend)
{
    constexpr int PAD = 20;
    float* As = sm;               // [64][20]
    float* Ws = sm + 64 * PAD;    // [NT][20]
    const int tid = threadIdx.x;
    const int wid = tid >> 5, lane = tid & 31;
    const int lq = lane >> 2, lr = lane & 3;
    const int wm = (wid >> 2) * 32;
    const int wn = (wid & 3) * (NT / 4);
    constexpr int NJ = NT / 32;           // n8 tiles per warp (4 or 2)
    constexpr int WL = NT / 64;           // W float4 loads per thread (2 or 1)

    float d[2][NJ][4];
    #pragma unroll
    for (int i = 0; i < 2; i++)
        #pragma unroll
        for (int j = 0; j < NJ; j++)
            { d[i][j][0]=0.f; d[i][j][1]=0.f; d[i][j][2]=0.f; d[i][j][3]=0.f; }

    const int ar = tid >> 2;          // 0..63
    const int ac = (tid & 3) << 2;    // 0,4,8,12

    float4 apre, wpre[WL];
    apre = __ldcg((const float4*)(A + (long long)ar * lda + k0 + ac));
    #pragma unroll
    for (int j = 0; j < WL; j++)
        wpre[j] = *(const float4*)(W + (long long)(ar + j * 64) * ldw + k0 + ac);

    for (int kk = k0; kk < kend; kk += 16) {
        float* ap = As + ar * PAD + ac;
        ap[0] = __uint_as_float(f2tf(apre.x)); ap[1] = __uint_as_float(f2tf(apre.y));
        ap[2] = __uint_as_float(f2tf(apre.z)); ap[3] = __uint_as_float(f2tf(apre.w));
        #pragma unroll
        for (int j = 0; j < WL; j++) {
            float* wp = Ws + (ar + j * 64) * PAD + ac;
            wp[0] = __uint_as_float(f2tf(wpre[j].x)); wp[1] = __uint_as_float(f2tf(wpre[j].y));
            wp[2] = __uint_as_float(f2tf(wpre[j].z)); wp[3] = __uint_as_float(f2tf(wpre[j].w));
        }
        __syncthreads();
        if (kk + 16 < kend) {
            apre = __ldcg((const float4*)(A + (long long)ar * lda + kk + 16 + ac));
            #pragma unroll
            for (int j = 0; j < WL; j++)
                wpre[j] = *(const float4*)(W + (long long)(ar + j * 64) * ldw + kk + 16 + ac);
        }
        #pragma unroll
        for (int k8 = 0; k8 < 16; k8 += 8) {
            uint32_t a[2][4];
            #pragma unroll
            for (int i = 0; i < 2; i++) {
                const float* p = As + (wm + i * 16 + lq) * PAD + k8 + lr;
                a[i][0] = __float_as_uint(p[0]);
                a[i][1] = __float_as_uint(p[8 * PAD]);
                a[i][2] = __float_as_uint(p[4]);
                a[i][3] = __float_as_uint(p[8 * PAD + 4]);
            }
            #pragma unroll
            for (int j = 0; j < NJ; j++) {
                const float* q = Ws + (wn + j * 8 + lq) * PAD + k8 + lr;
                uint32_t b[2] = { __float_as_uint(q[0]), __float_as_uint(q[4]) };
                #pragma unroll
                for (int i = 0; i < 2; i++) mma8(d[i][j], a[i], b);
            }
        }
        __syncthreads();
    }

    #pragma unroll
    for (int i = 0; i < 2; i++) {
        int row = wm + i * 16 + lq;
        #pragma unroll
        for (int j = 0; j < NJ; j++) {
            int col = wn + j * 8 + lr * 2;
            float b0 = 0.f, b1 = 0.f;
            if (bias) { b0 = bias[col]; b1 = bias[col + 1]; }
            float2 v0 = make_float2(d[i][j][0] + b0, d[i][j][1] + b1);
            float2 v1 = make_float2(d[i][j][2] + b0, d[i][j][3] + b1);
            *(float2*)(C + (long long)row * ldc + col) = v0;
            *(float2*)(C + (long long)(row + 8) * ldc + col) = v1;
        }
    }
}

// ---------------- tiny utility kernels ----------------
__global__ void k_init(float* h) {
    int i = blockIdx.x * 256 + threadIdx.x;   // 131072 threads
    h[i] = 0.f;
    if (i < 4) g_cnt[i] = 0u;
}

__global__ void k_embed(const int* __restrict__ src, const float* __restrict__ emb,
                        float* __restrict__ xs) {
    int i = blockIdx.x * 256 + threadIdx.x;
    int e = i & 255;
    int b = (i >> 8) & 63;
    int t = i >> 14;
    xs[i] = emb[src[b * Ss + t] * Ee + e];
}

__global__ void k_decprep(const float* __restrict__ henc,
                          float* __restrict__ h0, float* __restrict__ h1,
                          const float* __restrict__ enc_out,
                          const float* __restrict__ attn_W,
                          const float* __restrict__ attn_b,
                          float* __restrict__ enc_score,
                          float* __restrict__ out)
{
    long long gi0 = (long long)blockIdx.x * 256 + threadIdx.x;
    if (gi0 < 131072) {
        int k = (int)(gi0 & 1023);
        int b = (int)((gi0 >> 10) & 63);
        int layer = (int)(gi0 >> 16);
        int dir = k >> 9;
        float v = henc[layer * 2 * Bb * Hh + dir * Bb * Hh + b * Hh + (k & 511)];
        (layer ? h1 : h0)[b * Dd + k] = v;
    }
    if (gi0 < 524288) {
        int b = (int)(gi0 >> 13);
        out[(long long)b * Tt * VTt + (gi0 & 8191)] = 0.f;
    }
    {
        int wrp = (int)(gi0 >> 5);
        int lane = threadIdx.x & 31;
        const float* row = enc_out + (long long)wrp * 1024;
        float s = 0.f;
        for (int k = lane; k < 1024; k += 32)
            s += row[k] * attn_W[1024 + k];
        #pragma unroll
        for (int o = 16; o > 0; o >>= 1)
            s += __shfl_down_sync(0xffffffffu, s, o);
        if (lane == 0) enc_score[wrp] = s + attn_b[0];
    }
}

// ---------------- big tf32 GEMM (time-parallel gi projections) -------------
// C(M,1536) = A(M,K) @ W(1536,K)^T + bias.  grid (12, M/64)
__global__ void __launch_bounds__(256) k_gemm_big(
    const float* __restrict__ A, int lda,
    const float* __restrict__ W,
    const float* __restrict__ bias,
    float* __restrict__ C, int K)
{
    __shared__ float sm[(64 + 128) * 20];
    const int nt = blockIdx.x, mt = blockIdx.y;
    mma_tile<128>(sm, A + (long long)mt * 64 * lda, lda,
                  W + (long long)nt * 128 * K, K,
                  C + (long long)mt * 64 * 1536 + nt * 128, 1536,
                  bias + nt * 128, 0, K);
}

// ---------------- persistent encoder layer (grid = 144 blocks) -------------
// jobs: 3 ksplit x 2 dir x 24 n64-tiles = 144
__global__ void __launch_bounds__(256) k_enc(
    const float* __restrict__ gi, const float* __restrict__ Whh,
    const float* __restrict__ bhh, float* __restrict__ h,
    float* __restrict__ y, float* __restrict__ ghp, int mode, unsigned* cnt)
{
    __shared__ float sm[(64 + 64) * 20];
    const int bid = blockIdx.x;
    unsigned bt = 0;

    const int z = bid / 48, rem = bid % 48;
    const int dir = rem / 24, nt = rem % 24;
    const int k0 = z * 176, kend = (z == 2) ? 512 : (k0 + 176);
    const float* Ah = h + dir * 64 * 512;
    const float* Wt = Whh + (long long)dir * 1536 * 512 + (long long)nt * 64 * 512;
    float* Ct = ghp + (long long)z * 128 * 1536 + (long long)dir * 64 * 1536 + nt * 64;

    for (int t = 0; t < Ss; t++) {
        mma_tile<64>(sm, Ah, 512, Wt, 512, Ct, 1536, nullptr, k0, kend);
        gsync(cnt, bt += 144);

        for (int i = bid * 256 + threadIdx.x; i < 65536; i += 144 * 256) {
            int k = i & 511;
            int b = (i >> 9) & 63;
            int d2 = i >> 15;
            int row = d2 * 64 + b;
            int teff = d2 ? (255 - t) : t;

            long long gbase = ((long long)d2 * SB + (long long)teff * 64 + b) * 1536;
            float ir  = gi[gbase + k];
            float iz  = gi[gbase + 512 + k];
            float in_ = gi[gbase + 1024 + k];

            float hr = bhh[d2 * 1536 + k];
            float hz = bhh[d2 * 1536 + 512 + k];
            float hn = bhh[d2 * 1536 + 1024 + k];
            #pragma unroll
            for (int zz = 0; zz < 3; zz++) {
                long long p = (long long)zz * 128 * 1536 + (long long)row * 1536;
                hr += __ldcg(&ghp[p + k]);
                hz += __ldcg(&ghp[p + 512 + k]);
                hn += __ldcg(&ghp[p + 1024 + k]);
            }

            float hv = __ldcg(&h[row * 512 + k]);
            float r  = 1.f / (1.f + expf(-(ir + hr)));
            float zg = 1.f / (1.f + expf(-(iz + hz)));
            float n  = tanhf(in_ + r * hn);
            float hnew = (1.f - zg) * n + zg * hv;
            h[row * 512 + k] = hnew;

            if (mode == 0)
                y[((long long)teff * 64 + b) * 1024 + d2 * 512 + k] = hnew;
            else
                y[(long long)b * Ss * Dd + (long long)teff * Dd + d2 * 512 + k] = hnew;
        }
        gsync(cnt, bt += 144);
    }
}

// ---------------- decoder GRU combine ----------------
__device__ __forceinline__ void dec_combine(
    const float* __restrict__ gi_, int ngi,
    const float* __restrict__ gh_, int ngh,
    const float* __restrict__ bih, const float* __restrict__ bhh,
    float* __restrict__ h)
{
    for (int i = blockIdx.x * 256 + threadIdx.x; i < 65536; i += 148 * 256) {
        int k = i & 1023;
        int b = i >> 10;
        float ir = bih[k], iz = bih[1024 + k], in_ = bih[2048 + k];
        float hr = bhh[k], hz = bhh[1024 + k], hn  = bhh[2048 + k];
        for (int z = 0; z < ngi; z++) {
            long long p = (long long)z * 64 * 3072 + (long long)b * 3072;
            ir += __ldcg(&gi_[p + k]); iz += __ldcg(&gi_[p + 1024 + k]); in_ += __ldcg(&gi_[p + 2048 + k]);
        }
        for (int z = 0; z < ngh; z++) {
            long long p = (long long)z * 64 * 3072 + (long long)b * 3072;
            hr += __ldcg(&gh_[p + k]); hz += __ldcg(&gh_[p + 1024 + k]); hn += __ldcg(&gh_[p + 2048 + k]);
        }
        float hv = __ldcg(&h[b * 1024 + k]);
        float r  = 1.f / (1.f + expf(-(ir + hr)));
        float zg = 1.f / (1.f + expf(-(iz + hz)));
        float n  = tanhf(in_ + r * hn);
        h[b * 1024 + k] = (1.f - zg) * n + zg * hv;
    }
}

// ---------------- persistent decoder (grid = 148 blocks) -------------------
__global__ void __launch_bounds__(256) k_dec(
    const float* __restrict__ enc_out, const float* __restrict__ enc_score,
    const int* __restrict__ tgt, const float* __restrict__ tgt_emb,
    const float* __restrict__ attn_W,
    const float* __restrict__ dWih0, const float* __restrict__ dWhh0,
    const float* __restrict__ dbih0, const float* __restrict__ dbhh0,
    const float* __restrict__ dWih1, const float* __restrict__ dWhh1,
    const float* __restrict__ dbih1, const float* __restrict__ dbhh1,
    const float* __restrict__ out_W, const float* __restrict__ out_b,
    float* __restrict__ dh0, float* __restrict__ dh1,
    float* __restrict__ xdec,
    float* __restrict__ gpa, float* __restrict__ gpb, float* __restrict__ gpc,
    float* __restrict__ out, unsigned* cnt)
{
    __shared__ float sm[(64 + 128) * 20];
    __shared__ float red[256];
    __shared__ float sc[256];
    const int bid = blockIdx.x;
    const int tid = threadIdx.x;
    unsigned bt = 0;

    for (int t = 0; t < Tt - 1; t++) {
        // ---- Phase A: logits(t-1) [64 jobs] + attention(t) [64 jobs] ----
        if (bid < 64) {
            if (t > 0)
                mma_tile<128>(sm, dh1, 1024, out_W + (long long)bid * 128 * 1024, 1024,
                              out + (long long)t * VTt + bid * 128, (long long)Tt * VTt,
                              out_b + bid * 128, 0, 1024);
        } else if (bid < 128) {
            int b = bid - 64;
            float p = 0.f;
            #pragma unroll
            for (int j = tid; j < 1024; j += 256)
                p += __ldcg(&dh1[b * 1024 + j]) * attn_W[j];
            red[tid] = p; __syncthreads();
            for (int q = 128; q > 0; q >>= 1) { if (tid < q) red[tid] += red[tid + q]; __syncthreads(); }
            float qv = red[0];
            __syncthreads();

            float v = enc_score[b * 256 + tid] + qv;
            red[tid] = v; __syncthreads();
            for (int q = 128; q > 0; q >>= 1) { if (tid < q) red[tid] = fmaxf(red[tid], red[tid + q]); __syncthreads(); }
            float mx = red[0];
            __syncthreads();
            float e = expf(v - mx);
            red[tid] = e; __syncthreads();
            for (int q = 128; q > 0; q >>= 1) { if (tid < q) red[tid] += red[tid + q]; __syncthreads(); }
            sc[tid] = e / red[0];
            __syncthreads();

            float4 acc = make_float4(0.f, 0.f, 0.f, 0.f);
            const float4* eo = (const float4*)(enc_out + (long long)b * Ss * Dd);
            #pragma unroll 4
            for (int sIdx = 0; sIdx < 256; sIdx++) {
                float w = sc[sIdx];
                float4 ev = eo[sIdx * 256 + tid];
                acc.x += w * ev.x; acc.y += w * ev.y; acc.z += w * ev.z; acc.w += w * ev.w;
            }
            *(float4*)&xdec[b * 1280 + 256 + tid * 4] = acc;
            xdec[b * 1280 + tid] = tgt_emb[tgt[b * Tt + t] * 256 + tid];
        }
        gsync(cnt, bt += 148);

        // ---- Phase B: gi0 (72 jobs, K=1280 split3) + gh0 (72) + gh1 (72) ----
        for (int job = bid; job < 216; job += 148) {
            if (job < 72) {
                int z = job / 24, nt = job % 24;
                int k0 = z * 432, ke = (z == 2) ? 1280 : (k0 + 432);
                mma_tile<128>(sm, xdec, 1280, dWih0 + (long long)nt * 128 * 1280, 1280,
                              gpa + (long long)z * 64 * 3072 + nt * 128, 3072, nullptr, k0, ke);
            } else if (job < 144) {
                int j = job - 72; int z = j / 24, nt = j % 24;
                int k0 = (z == 0) ? 0 : (z == 1 ? 352 : 688);
                int ke = (z == 0) ? 352 : (z == 1 ? 688 : 1024);
                mma_tile<128>(sm, dh0, 1024, dWhh0 + (long long)nt * 128 * 1024, 1024,
                              gpb + (long long)z * 64 * 3072 + nt * 128, 3072, nullptr, k0, ke);
            } else {
                int j = job - 144; int z = j / 24, nt = j % 24;
                int k0 = (z == 0) ? 0 : (z == 1 ? 352 : 688);
                int ke = (z == 0) ? 352 : (z == 1 ? 688 : 1024);
                mma_tile<128>(sm, dh1, 1024, dWhh1 + (long long)nt * 128 * 1024, 1024,
                              gpc + (long long)z * 64 * 3072 + nt * 128, 3072, nullptr, k0, ke);
            }
        }
        gsync(cnt, bt += 148);

        // ---- Phase C: combine h0 ----
        dec_combine(gpa, 3, gpb, 3, dbih0, dbhh0, dh0);
        gsync(cnt, bt += 148);

        // ---- Phase D: gi1 (144 jobs, K=1024 split6) ----
        for (int job = bid; job < 144; job += 148) {
            int z = job / 24, nt = job % 24;
            int k0 = (z < 4) ? z * 176 : 704 + (z - 4) * 160;
            int ke = k0 + ((z < 4) ? 176 : 160);
            mma_tile<128>(sm, dh0, 1024, dWih1 + (long long)nt * 128 * 1024, 1024,
                          gpa + (long long)z * 64 * 3072 + nt * 128, 3072, nullptr, k0, ke);
        }
        gsync(cnt, bt += 148);

        // ---- Phase E: combine h1 ----
        dec_combine(gpa, 6, gpc, 3, dbih1, dbhh1, dh1);
        gsync(cnt, bt += 148);
    }

    // ---- final logits (t = 126 -> out[:, 127, :]) ----
    if (bid < 64)
        mma_tile<128>(sm, dh1, 1024, out_W + (long long)bid * 128 * 1024, 1024,
                      out + (long long)127 * VTt + bid * 128, (long long)Tt * VTt,
                      out_b + bid * 128, 0, 1024);
}

extern "C" void kernel_launch(void* const* d_in, const int* in_sizes, int n_in,
                              void* d_out, int out_size)
{
    const int*   src     = (const int*)  d_in[0];
    const int*   tgt     = (const int*)  d_in[1];
    const float* src_emb = (const float*)d_in[2];
    const float* tgt_emb = (const float*)d_in[3];
    const float* eWih0   = (const float*)d_in[4];
    const float* eWhh0   = (const float*)d_in[5];
    const float* ebih0   = (const float*)d_in[6];
    const float* ebhh0   = (const float*)d_in[7];
    const float* eWih1   = (const float*)d_in[8];
    const float* eWhh1   = (const float*)d_in[9];
    const float* ebih1   = (const float*)d_in[10];
    const float* ebhh1   = (const float*)d_in[11];
    const float* dWih0   = (const float*)d_in[12];
    const float* dWhh0   = (const float*)d_in[13];
    const float* dbih0   = (const float*)d_in[14];
    const float* dbhh0   = (const float*)d_in[15];
    const float* dWih1   = (const float*)d_in[16];
    const float* dWhh1   = (const float*)d_in[17];
    const float* dbih1   = (const float*)d_in[18];
    const float* dbhh1   = (const float*)d_in[19];
    const float* attn_W  = (const float*)d_in[20];
    const float* attn_b  = (const float*)d_in[21];
    const float* out_W   = (const float*)d_in[22];
    const float* out_b   = (const float*)d_in[23];
    float* out = (float*)d_out;

    float *xs, *gi, *y0, *enc_out, *enc_sc, *h, *ghp, *dh0, *dh1, *xdec, *gpa, *gpb, *gpc;
    unsigned* cnt;
    cudaGetSymbolAddress((void**)&xs,      g_xs);
    cudaGetSymbolAddress((void**)&gi,      g_gi);
    cudaGetSymbolAddress((void**)&y0,      g_y0);
    cudaGetSymbolAddress((void**)&enc_out, g_enc_out);
    cudaGetSymbolAddress((void**)&enc_sc,  g_enc_score);
    cudaGetSymbolAddress((void**)&h,       g_h);
    cudaGetSymbolAddress((void**)&ghp,     g_ghp);
    cudaGetSymbolAddress((void**)&dh0,     g_dh0);
    cudaGetSymbolAddress((void**)&dh1,     g_dh1);
    cudaGetSymbolAddress((void**)&xdec,    g_xdec);
    cudaGetSymbolAddress((void**)&gpa,     g_gpa);
    cudaGetSymbolAddress((void**)&gpb,     g_gpb);
    cudaGetSymbolAddress((void**)&gpc,     g_gpc);
    cudaGetSymbolAddress((void**)&cnt,     g_cnt);

    // ---- setup ----
    k_init<<<512, 256>>>(h);
    k_embed<<<(SB * Ee) / 256, 256>>>(src, src_emb, xs);

    // ---- encoder layer 0 ----
    for (int d = 0; d < 2; d++)
        k_gemm_big<<<dim3(12, SB / 64), 256>>>(xs, Ee, eWih0 + (size_t)d * 1536 * Ee,
                                               ebih0 + d * 1536,
                                               gi + (size_t)d * SB * 1536, Ee);
    k_enc<<<144, 256>>>(gi, eWhh0, ebhh0, h, y0, ghp, 0, cnt);

    // ---- encoder layer 1 ----
    for (int d = 0; d < 2; d++)
        k_gemm_big<<<dim3(12, SB / 64), 256>>>(y0, Dd, eWih1 + (size_t)d * 1536 * Dd,
                                               ebih1 + d * 1536,
                                               gi + (size_t)d * SB * 1536, Dd);
    k_enc<<<144, 256>>>(gi, eWhh1, ebhh1, h + 2 * Bb * Hh, enc_out, ghp, 1, cnt + 1);

    // ---- decoder prep ----
    k_decprep<<<2048, 256>>>(h, dh0, dh1, enc_out, attn_W, attn_b, enc_sc, out);

    // ---- decoder (persistent) ----
    k_dec<<<148, 256>>>(enc_out, enc_sc, tgt, tgt_emb, attn_W,
                        dWih0, dWhh0, dbih0, dbhh0,
                        dWih1, dWhh1, dbih1, dbhh1,
                        out_W, out_b, dh0, dh1, xdec, gpa, gpb, gpc, out, cnt + 2);
}